// round 15
// baseline (speedup 1.0000x reference)
#include <cuda_runtime.h>
#include <cuda_fp16.h>

// CapsuleLayer dynamic routing — BT=2, full-line W with packed fma.f32x2,
// fp16 pair-packed P (fp32 logits/E), no-max softmax, 512 thr, 2 CTAs/SM.
// x: [256, 1152, 8] f32 ; W: [10, 1152, 8, 16] f32 ; out: [256, 10, 16] f32
#define NB 256
#define NC 10
#define NR 1152
#define IC 8
#define OC 16
#define THREADS 512
#define NWARP 16
#define BT 2
#define PSTR2 1154                // Pp row stride in half2 units (≡2 mod 32)
#define P2_UNITS (OC * PSTR2)
#define NUM_ITER 3

// SMEM 4B units: Pp | E0[1156] | E1[1156] | red2[16*33] | S2[32] | V[32] | red[64] | aux[8]
#define SMEM_FLOATS (P2_UNITS + 2 * 1156 + 16 * 33 + 32 + 32 + 64 + 8)

typedef unsigned long long u64;

__device__ __forceinline__ u64 bcast2(float v) {
    u64 r; asm("mov.b64 %0, {%1, %1};" : "=l"(r) : "f"(v)); return r;
}
__device__ __forceinline__ float2 unpack2(u64 v) {
    float2 f; asm("mov.b64 {%0, %1}, %2;" : "=f"(f.x), "=f"(f.y) : "l"(v)); return f;
}
__device__ __forceinline__ u64 mul2_(u64 a, u64 b) {
    u64 d; asm("mul.rn.f32x2 %0, %1, %2;" : "=l"(d) : "l"(a), "l"(b)); return d;
}
__device__ __forceinline__ u64 fma2_(u64 a, u64 b, u64 c) {
    u64 d; asm("fma.rn.f32x2 %0, %1, %2, %3;" : "=l"(d) : "l"(a), "l"(b), "l"(c)); return d;
}
__device__ __forceinline__ u64 add2_(u64 a, u64 b) {
    u64 d; asm("add.rn.f32x2 %0, %1, %2;" : "=l"(d) : "l"(a), "l"(b)); return d;
}
__device__ __forceinline__ __half2 shfl_xor_h2(__half2 v, int off) {
    unsigned u = *reinterpret_cast<unsigned*>(&v);
    u = __shfl_xor_sync(0xFFFFFFFFu, u, off);
    return *reinterpret_cast<__half2*>(&u);
}

extern "C" __global__ void __launch_bounds__(THREADS, 2)
caps_route_kernel(const float* __restrict__ x,
                  const float* __restrict__ W,
                  float* __restrict__ out)
{
    extern __shared__ float sm[];
    __half2* Pp   = reinterpret_cast<__half2*>(sm);        // [oc][r], x=b0 y=b1
    float*   E0   = sm + P2_UNITS;                         // fp32 probs b0
    float*   E1   = E0 + 1156;                             // fp32 probs b1
    float*   red2 = E1 + 1156;                             // [16][33]
    float*   S2   = red2 + 16 * 33;                        // [b*16+oc]
    float*   V    = S2 + 32;                               // fp32 outputs
    float*   red  = V + 32;
    float*   aux  = red + 64;

    const int tid  = threadIdx.x;
    const int lane = tid & 31;
    const int wid  = tid >> 5;

    const int b0 = blockIdx.x * BT;
    const int c  = blockIdx.y;

    const float* xb0 = x + (size_t)b0 * NR * IC;
    const float* xb1 = xb0 + NR * IC;
    const ulonglong2* Wc2 = reinterpret_cast<const ulonglong2*>(
                                W + (size_t)c * NR * IC * OC);

    // ============ Phase 1: priors — full-line W, packed f32x2 FMA ============
    // lane = rloc*8 + q ; q = qi*4 + sub. Warp owns 4 rows/chunk, 18 chunks.
    // W float4 (LDG.128) gives free (oc0,oc1)/(oc2,oc3) 64-bit pairs; accs are
    // oc-pair-packed f32x2; qi twins merge in half2 and split packed stores.
    {
        const int rloc  = lane >> 3;
        const int q     = lane & 7;
        const int qi    = q >> 2;
        const int sub   = q & 3;
        const int rbase = wid * 4 + rloc;

        u64 s01A = 0, s23A = 0, s01B = 0, s23B = 0;   // packed iter0 sums

        #pragma unroll 3
        for (int it = 0; it < 18; ++it) {
            const int r = rbase + it * 64;
            const ulonglong2* wp = Wc2 + (size_t)r * 32 + q;
            const ulonglong2 w0 = wp[0];     // i-pair 0, this lane's oc quad
            const ulonglong2 w1 = wp[8];
            const ulonglong2 w2 = wp[16];
            const ulonglong2 w3 = wp[24];
            const float* xrA = xb0 + r * IC + qi;
            const float* xrB = xb1 + r * IC + qi;
            const u64 xA0 = bcast2(xrA[0]);
            const u64 xA1 = bcast2(xrA[2]);
            const u64 xA2 = bcast2(xrA[4]);
            const u64 xA3 = bcast2(xrA[6]);
            const u64 xB0 = bcast2(xrB[0]);
            const u64 xB1 = bcast2(xrB[2]);
            const u64 xB2 = bcast2(xrB[4]);
            const u64 xB3 = bcast2(xrB[6]);

            u64 a01A = mul2_(xA0, w0.x);
            u64 a23A = mul2_(xA0, w0.y);
            u64 a01B = mul2_(xB0, w0.x);
            u64 a23B = mul2_(xB0, w0.y);
            a01A = fma2_(xA1, w1.x, a01A);  a23A = fma2_(xA1, w1.y, a23A);
            a01B = fma2_(xB1, w1.x, a01B);  a23B = fma2_(xB1, w1.y, a23B);
            a01A = fma2_(xA2, w2.x, a01A);  a23A = fma2_(xA2, w2.y, a23A);
            a01B = fma2_(xB2, w2.x, a01B);  a23B = fma2_(xB2, w2.y, a23B);
            a01A = fma2_(xA3, w3.x, a01A);  a23A = fma2_(xA3, w3.y, a23A);
            a01B = fma2_(xB3, w3.x, a01B);  a23B = fma2_(xB3, w3.y, a23B);

            // pack to half2(b0,b1) per oc, merge i-parities in fp16
            const float2 fA01 = unpack2(a01A);
            const float2 fA23 = unpack2(a23A);
            const float2 fB01 = unpack2(a01B);
            const float2 fB23 = unpack2(a23B);
            __half2 h0 = __floats2half2_rn(fA01.x, fB01.x);
            __half2 h1 = __floats2half2_rn(fA01.y, fB01.y);
            __half2 h2 = __floats2half2_rn(fA23.x, fB23.x);
            __half2 h3 = __floats2half2_rn(fA23.y, fB23.y);
            h0 = __hadd2(h0, shfl_xor_h2(h0, 4));
            h1 = __hadd2(h1, shfl_xor_h2(h1, 4));
            h2 = __hadd2(h2, shfl_xor_h2(h2, 4));
            h3 = __hadd2(h3, shfl_xor_h2(h3, 4));

            // twins split the stores: qi=0 -> h0,h1 ; qi=1 -> h2,h3
            const __half2 st0 = qi ? h2 : h0;
            const __half2 st1 = qi ? h3 : h1;
            const int ob = sub * 4 + qi * 2;
            Pp[(ob + 0) * PSTR2 + r] = st0;
            Pp[(ob + 1) * PSTR2 + r] = st1;

            // iter0 sums: packed fp32 adds on pre-merge partials (exact)
            s01A = add2_(s01A, a01A);  s23A = add2_(s23A, a23A);
            s01B = add2_(s01B, a01B);  s23B = add2_(s23B, a23B);
        }

        // unpack sums; reduce over qi (bit 2) and rloc (bits 3,4)
        const float2 u01A = unpack2(s01A), u23A = unpack2(s23A);
        const float2 u01B = unpack2(s01B), u23B = unpack2(s23B);
        float sA0 = u01A.x, sA1 = u01A.y, sA2 = u23A.x, sA3 = u23A.y;
        float sB0 = u01B.x, sB1 = u01B.y, sB2 = u23B.x, sB3 = u23B.y;
        #pragma unroll
        for (int off = 4; off <= 16; off <<= 1) {
            sA0 += __shfl_xor_sync(0xFFFFFFFFu, sA0, off);
            sA1 += __shfl_xor_sync(0xFFFFFFFFu, sA1, off);
            sA2 += __shfl_xor_sync(0xFFFFFFFFu, sA2, off);
            sA3 += __shfl_xor_sync(0xFFFFFFFFu, sA3, off);
            sB0 += __shfl_xor_sync(0xFFFFFFFFu, sB0, off);
            sB1 += __shfl_xor_sync(0xFFFFFFFFu, sB1, off);
            sB2 += __shfl_xor_sync(0xFFFFFFFFu, sB2, off);
            sB3 += __shfl_xor_sync(0xFFFFFFFFu, sB3, off);
        }
        if (lane < 4) {           // rloc=0, qi=0, sub=lane
            float* row = red2 + wid * 33;
            row[lane * 4 + 0] = sA0;  row[lane * 4 + 1] = sA1;
            row[lane * 4 + 2] = sA2;  row[lane * 4 + 3] = sA3;
            row[16 + lane * 4 + 0] = sB0;  row[16 + lane * 4 + 1] = sB1;
            row[16 + lane * 4 + 2] = sB2;  row[16 + lane * 4 + 3] = sB3;
        }
    }
    __syncthreads();

    // ============ iter 0: squash from fused fp32 sums ========================
    const float inv_nr = 1.0f / (float)NR;
    if (wid == 0) {
        float s = 0.f;
        #pragma unroll
        for (int w2 = 0; w2 < NWARP; ++w2) s += red2[w2 * 33 + lane];
        float sv = s * inv_nr;
        float sq = sv * sv;
        #pragma unroll
        for (int off = 8; off > 0; off >>= 1)
            sq += __shfl_xor_sync(0xFFFFFFFFu, sq, off);   // within 16-half
        const float sc = sq / ((1.f + sq) * sqrtf(sq));
        V[lane] = sv * sc;
    }
    __syncthreads();

    // ============ Phase 2: routing iterations 1..2 (fp32 logit path) =========
    const int  ra   = tid;
    const int  rb   = tid + THREADS;
    const int  rc   = tid + 2 * THREADS;
    const bool hasc = (tid < NR - 2 * THREADS);   // tid < 128

    float La0 = 0.f, La1 = 0.f;
    float Lb0 = 0.f, Lb1 = 0.f;
    float Lc0 = 0.f, Lc1 = 0.f;

    for (int iter = 1; iter < NUM_ITER; ++iter) {
        // ---- delta logits: fp32 unpack + FMA (precision-critical path) ----
        {
            const float4* V4 = reinterpret_cast<const float4*>(V);
            float da0 = 0.f, da1 = 0.f, db0 = 0.f, db1 = 0.f;
            float dc0 = 0.f, dc1 = 0.f;
            #pragma unroll
            for (int o4 = 0; o4 < 4; ++o4) {
                const float4 v0 = V4[o4];
                const float4 v1 = V4[4 + o4];
                const float v0a[4] = {v0.x, v0.y, v0.z, v0.w};
                const float v1a[4] = {v1.x, v1.y, v1.z, v1.w};
                #pragma unroll
                for (int j = 0; j < 4; ++j) {
                    const int oc = o4 * 4 + j;
                    const float2 f = __half22float2(Pp[oc * PSTR2 + ra]);
                    da0 = fmaf(f.x, v0a[j], da0);
                    da1 = fmaf(f.y, v1a[j], da1);
                    const float2 g = __half22float2(Pp[oc * PSTR2 + rb]);
                    db0 = fmaf(g.x, v0a[j], db0);
                    db1 = fmaf(g.y, v1a[j], db1);
                    if (hasc) {
                        const float2 h = __half22float2(Pp[oc * PSTR2 + rc]);
                        dc0 = fmaf(h.x, v0a[j], dc0);
                        dc1 = fmaf(h.y, v1a[j], dc1);
                    }
                }
            }
            La0 += da0; La1 += da1;
            Lb0 += db0; Lb1 += db1;
            Lc0 += dc0; Lc1 += dc1;
        }

        // ---- softmax WITHOUT max-pass: |L| bounded << 88, exp in fp32 ----
        {
            float s0, s1;
            {
                const float ea0 = __expf(La0);
                const float ea1 = __expf(La1);
                const float eb0 = __expf(Lb0);
                const float eb1 = __expf(Lb1);
                E0[ra] = ea0; E1[ra] = ea1;
                E0[rb] = eb0; E1[rb] = eb1;
                s0 = ea0 + eb0; s1 = ea1 + eb1;
                if (hasc) {
                    const float ec0 = __expf(Lc0);
                    const float ec1 = __expf(Lc1);
                    E0[rc] = ec0; E1[rc] = ec1;
                    s0 += ec0; s1 += ec1;
                }
            }
            #pragma unroll
            for (int off = 16; off > 0; off >>= 1) {
                s0 += __shfl_xor_sync(0xFFFFFFFFu, s0, off);
                s1 += __shfl_xor_sync(0xFFFFFFFFu, s1, off);
            }
            if (lane == 0) { red[wid] = s0; red[32 + wid] = s1; }
            __syncthreads();
            if (wid < 2) {
                float v = (lane < NWARP) ? red[wid * 32 + lane] : 0.f;
                #pragma unroll
                for (int off = 8; off > 0; off >>= 1)
                    v += __shfl_xor_sync(0xFFFFFFFFu, v, off);
                if (lane == 0) aux[wid] = 1.0f / v;
            }
            __syncthreads();   // E + aux visible
        }

        // ---- weighted sum: warp = oc; fp32 E, half2 P ----
        {
            const __half2* pc = Pp + wid * PSTR2;
            float a0 = 0.f, a1 = 0.f;
            #pragma unroll 4
            for (int rr = lane; rr < NR; rr += 32) {
                const float2 p = __half22float2(pc[rr]);
                a0 = fmaf(E0[rr], p.x, a0);
                a1 = fmaf(E1[rr], p.y, a1);
            }
            #pragma unroll
            for (int off = 16; off > 0; off >>= 1) {
                a0 += __shfl_xor_sync(0xFFFFFFFFu, a0, off);
                a1 += __shfl_xor_sync(0xFFFFFFFFu, a1, off);
            }
            if (lane == 0) {
                S2[wid]      = a0;   // batch 0
                S2[16 + wid] = a1;   // batch 1
            }
        }
        __syncthreads();

        // ---- squash (warp 0; lanes 0-15 b0, 16-31 b1) ----
        if (wid == 0) {
            float sv = S2[lane] * aux[lane >> 4];
            float sq = sv * sv;
            #pragma unroll
            for (int off = 8; off > 0; off >>= 1)
                sq += __shfl_xor_sync(0xFFFFFFFFu, sq, off);
            const float sc = sq / ((1.f + sq) * sqrtf(sq));
            V[lane] = sv * sc;
        }
        __syncthreads();
    }

    // ============ Phase 3: output ============================================
    if (tid < 2 * OC) {
        const int obb = tid >> 4;
        out[((size_t)(b0 + obb) * NC + c) * OC + (tid & 15)] = V[tid];
    }
}

extern "C" void kernel_launch(void* const* d_in, const int* in_sizes, int n_in,
                              void* d_out, int out_size)
{
    (void)in_sizes; (void)n_in; (void)out_size;
    const float* x = (const float*)d_in[0];
    const float* W = (const float*)d_in[1];
    float* out = (float*)d_out;

    static int smem_set = 0;
    const int smem_bytes = SMEM_FLOATS * sizeof(float);
    if (!smem_set) {
        cudaFuncSetAttribute(caps_route_kernel,
                             cudaFuncAttributeMaxDynamicSharedMemorySize,
                             smem_bytes);
        smem_set = 1;
    }

    dim3 grid(NB / BT, NC);
    caps_route_kernel<<<grid, THREADS, smem_bytes>>>(x, W, out);
}

// round 17
// speedup vs baseline: 1.0511x; 1.0511x over previous
#include <cuda_runtime.h>
#include <cuda_fp16.h>

// CapsuleLayer dynamic routing — BT=2, full-line W (scalar FMA), fp16
// pair-packed P, fp32 logits/E, no-max softmax, paired WS. 512 thr, 2 CTAs/SM.
// x: [256, 1152, 8] f32 ; W: [10, 1152, 8, 16] f32 ; out: [256, 10, 16] f32
#define NB 256
#define NC 10
#define NR 1152
#define IC 8
#define OC 16
#define THREADS 512
#define NWARP 16
#define BT 2
#define PSTR2 1154                // Pp row stride in half2 units (≡2 mod 32)
#define P2_UNITS (OC * PSTR2)
#define NUM_ITER 3

// SMEM 4B units: Pp | E0[1156] | E1[1156] | red2[16*33] | S2[64] | V[32] | red[64] | aux[8]
#define SMEM_FLOATS (P2_UNITS + 2 * 1156 + 16 * 33 + 64 + 32 + 64 + 8)

__device__ __forceinline__ __half2 shfl_xor_h2(__half2 v, int off) {
    unsigned u = *reinterpret_cast<unsigned*>(&v);
    u = __shfl_xor_sync(0xFFFFFFFFu, u, off);
    return *reinterpret_cast<__half2*>(&u);
}

extern "C" __global__ void __launch_bounds__(THREADS, 2)
caps_route_kernel(const float* __restrict__ x,
                  const float* __restrict__ W,
                  float* __restrict__ out)
{
    extern __shared__ float sm[];
    __half2* Pp   = reinterpret_cast<__half2*>(sm);        // [oc][r], x=b0 y=b1
    float*   E0   = sm + P2_UNITS;                         // fp32 probs b0
    float*   E1   = E0 + 1156;                             // fp32 probs b1
    float*   red2 = E1 + 1156;                             // [16][33]
    float*   S2   = red2 + 16 * 33;                        // [rhalf][b*16+oc]
    float*   V    = S2 + 64;                               // fp32 outputs
    float*   red  = V + 32;
    float*   aux  = red + 64;

    const int tid  = threadIdx.x;
    const int lane = tid & 31;
    const int wid  = tid >> 5;

    const int b0 = blockIdx.x * BT;
    const int c  = blockIdx.y;

    const float*  xb0 = x + (size_t)b0 * NR * IC;
    const float*  xb1 = xb0 + NR * IC;
    const float4* Wc4 = reinterpret_cast<const float4*>(
                            W + (size_t)c * NR * IC * OC);

    // ============ Phase 1: priors — full-line W loads, half2 1-level merge ===
    // lane = rloc*8 + q ; q = qi*4 + sub. Warp owns 4 rows/chunk, 18 chunks.
    {
        const int rloc  = lane >> 3;
        const int q     = lane & 7;
        const int qi    = q >> 2;
        const int sub   = q & 3;
        const int rbase = wid * 4 + rloc;

        float sA0 = 0.f, sA1 = 0.f, sA2 = 0.f, sA3 = 0.f;  // pre-merge partials
        float sB0 = 0.f, sB1 = 0.f, sB2 = 0.f, sB3 = 0.f;

        #pragma unroll 3
        for (int it = 0; it < 18; ++it) {
            const int r = rbase + it * 64;
            const float4* wp = Wc4 + (size_t)r * 32 + q;
            const float4 w0 = wp[0];
            const float4 w1 = wp[8];
            const float4 w2 = wp[16];
            const float4 w3 = wp[24];
            // scalar qi-offset x loads (no selects)
            const float* xrA = xb0 + r * IC + qi;
            const float* xrB = xb1 + r * IC + qi;
            const float xA0 = xrA[0], xA1 = xrA[2], xA2 = xrA[4], xA3 = xrA[6];
            const float xB0 = xrB[0], xB1 = xrB[2], xB2 = xrB[4], xB3 = xrB[6];

            float aA0, aA1, aA2, aA3, aB0, aB1, aB2, aB3;
            aA0 = xA0 * w0.x; aA1 = xA0 * w0.y; aA2 = xA0 * w0.z; aA3 = xA0 * w0.w;
            aB0 = xB0 * w0.x; aB1 = xB0 * w0.y; aB2 = xB0 * w0.z; aB3 = xB0 * w0.w;
            aA0 = fmaf(xA1, w1.x, aA0); aA1 = fmaf(xA1, w1.y, aA1);
            aA2 = fmaf(xA1, w1.z, aA2); aA3 = fmaf(xA1, w1.w, aA3);
            aB0 = fmaf(xB1, w1.x, aB0); aB1 = fmaf(xB1, w1.y, aB1);
            aB2 = fmaf(xB1, w1.z, aB2); aB3 = fmaf(xB1, w1.w, aB3);
            aA0 = fmaf(xA2, w2.x, aA0); aA1 = fmaf(xA2, w2.y, aA1);
            aA2 = fmaf(xA2, w2.z, aA2); aA3 = fmaf(xA2, w2.w, aA3);
            aB0 = fmaf(xB2, w2.x, aB0); aB1 = fmaf(xB2, w2.y, aB1);
            aB2 = fmaf(xB2, w2.z, aB2); aB3 = fmaf(xB2, w2.w, aB3);
            aA0 = fmaf(xA3, w3.x, aA0); aA1 = fmaf(xA3, w3.y, aA1);
            aA2 = fmaf(xA3, w3.z, aA2); aA3 = fmaf(xA3, w3.w, aA3);
            aB0 = fmaf(xB3, w3.x, aB0); aB1 = fmaf(xB3, w3.y, aB1);
            aB2 = fmaf(xB3, w3.z, aB2); aB3 = fmaf(xB3, w3.w, aB3);

            // pack to half2(b0,b1), merge i-parities in fp16 (4 shfl + 4 hadd2)
            __half2 h0 = __floats2half2_rn(aA0, aB0);
            __half2 h1 = __floats2half2_rn(aA1, aB1);
            __half2 h2 = __floats2half2_rn(aA2, aB2);
            __half2 h3 = __floats2half2_rn(aA3, aB3);
            h0 = __hadd2(h0, shfl_xor_h2(h0, 4));
            h1 = __hadd2(h1, shfl_xor_h2(h1, 4));
            h2 = __hadd2(h2, shfl_xor_h2(h2, 4));
            h3 = __hadd2(h3, shfl_xor_h2(h3, 4));

            // twins split the stores: qi=0 -> h0,h1 ; qi=1 -> h2,h3
            const __half2 st0 = qi ? h2 : h0;
            const __half2 st1 = qi ? h3 : h1;
            const int ob = sub * 4 + qi * 2;
            Pp[(ob + 0) * PSTR2 + r] = st0;
            Pp[(ob + 1) * PSTR2 + r] = st1;

            // iter0 sums from fp32 pre-merge partials (exact path)
            sA0 += aA0; sA1 += aA1; sA2 += aA2; sA3 += aA3;
            sB0 += aB0; sB1 += aB1; sB2 += aB2; sB3 += aB3;
        }

        // reduce iter0 sums over qi (bit 2) and rloc (bits 3,4)
        #pragma unroll
        for (int off = 4; off <= 16; off <<= 1) {
            sA0 += __shfl_xor_sync(0xFFFFFFFFu, sA0, off);
            sA1 += __shfl_xor_sync(0xFFFFFFFFu, sA1, off);
            sA2 += __shfl_xor_sync(0xFFFFFFFFu, sA2, off);
            sA3 += __shfl_xor_sync(0xFFFFFFFFu, sA3, off);
            sB0 += __shfl_xor_sync(0xFFFFFFFFu, sB0, off);
            sB1 += __shfl_xor_sync(0xFFFFFFFFu, sB1, off);
            sB2 += __shfl_xor_sync(0xFFFFFFFFu, sB2, off);
            sB3 += __shfl_xor_sync(0xFFFFFFFFu, sB3, off);
        }
        if (lane < 4) {           // rloc=0, qi=0, sub=lane
            float* row = red2 + wid * 33;
            row[lane * 4 + 0] = sA0;  row[lane * 4 + 1] = sA1;
            row[lane * 4 + 2] = sA2;  row[lane * 4 + 3] = sA3;
            row[16 + lane * 4 + 0] = sB0;  row[16 + lane * 4 + 1] = sB1;
            row[16 + lane * 4 + 2] = sB2;  row[16 + lane * 4 + 3] = sB3;
        }
    }
    __syncthreads();

    // ============ iter 0: squash from fused fp32 sums ========================
    const float inv_nr = 1.0f / (float)NR;
    if (wid == 0) {
        float s = 0.f;
        #pragma unroll
        for (int w2 = 0; w2 < NWARP; ++w2) s += red2[w2 * 33 + lane];
        float sv = s * inv_nr;
        float sq = sv * sv;
        #pragma unroll
        for (int off = 8; off > 0; off >>= 1)
            sq += __shfl_xor_sync(0xFFFFFFFFu, sq, off);   // within 16-half
        const float sc = sq / ((1.f + sq) * sqrtf(sq));
        V[lane] = sv * sc;
    }
    __syncthreads();

    // ============ Phase 2: routing iterations 1..2 (fp32 logit path) =========
    const int  ra   = tid;
    const int  rb   = tid + THREADS;
    const int  rc   = tid + 2 * THREADS;
    const bool hasc = (tid < NR - 2 * THREADS);   // tid < 128

    float La0 = 0.f, La1 = 0.f;
    float Lb0 = 0.f, Lb1 = 0.f;
    float Lc0 = 0.f, Lc1 = 0.f;

    // WS mapping: warp = (r-half, oc-pair)
    const int wsop = wid & 7;
    const int wsrh = wid >> 3;
    const int woc0 = wsop * 2, woc1 = woc0 + 1;
    const int rst  = wsrh * (NR / 2);

    for (int iter = 1; iter < NUM_ITER; ++iter) {
        // ---- delta logits: fp32 unpack + FMA (precision-critical path) ----
        {
            const float4* V4 = reinterpret_cast<const float4*>(V);
            float da0 = 0.f, da1 = 0.f, db0 = 0.f, db1 = 0.f;
            float dc0 = 0.f, dc1 = 0.f;
            #pragma unroll
            for (int o4 = 0; o4 < 4; ++o4) {
                const float4 v0 = V4[o4];
                const float4 v1 = V4[4 + o4];
                const float v0a[4] = {v0.x, v0.y, v0.z, v0.w};
                const float v1a[4] = {v1.x, v1.y, v1.z, v1.w};
                #pragma unroll
                for (int j = 0; j < 4; ++j) {
                    const int oc = o4 * 4 + j;
                    const float2 f = __half22float2(Pp[oc * PSTR2 + ra]);
                    da0 = fmaf(f.x, v0a[j], da0);
                    da1 = fmaf(f.y, v1a[j], da1);
                    const float2 g = __half22float2(Pp[oc * PSTR2 + rb]);
                    db0 = fmaf(g.x, v0a[j], db0);
                    db1 = fmaf(g.y, v1a[j], db1);
                    if (hasc) {
                        const float2 h = __half22float2(Pp[oc * PSTR2 + rc]);
                        dc0 = fmaf(h.x, v0a[j], dc0);
                        dc1 = fmaf(h.y, v1a[j], dc1);
                    }
                }
            }
            La0 += da0; La1 += da1;
            Lb0 += db0; Lb1 += db1;
            Lc0 += dc0; Lc1 += dc1;
        }

        // ---- softmax WITHOUT max-pass: |L| bounded << 88, exp in fp32 ----
        {
            float s0, s1;
            {
                const float ea0 = __expf(La0);
                const float ea1 = __expf(La1);
                const float eb0 = __expf(Lb0);
                const float eb1 = __expf(Lb1);
                E0[ra] = ea0; E1[ra] = ea1;
                E0[rb] = eb0; E1[rb] = eb1;
                s0 = ea0 + eb0; s1 = ea1 + eb1;
                if (hasc) {
                    const float ec0 = __expf(Lc0);
                    const float ec1 = __expf(Lc1);
                    E0[rc] = ec0; E1[rc] = ec1;
                    s0 += ec0; s1 += ec1;
                }
            }
            #pragma unroll
            for (int off = 16; off > 0; off >>= 1) {
                s0 += __shfl_xor_sync(0xFFFFFFFFu, s0, off);
                s1 += __shfl_xor_sync(0xFFFFFFFFu, s1, off);
            }
            if (lane == 0) { red[wid] = s0; red[32 + wid] = s1; }
            __syncthreads();
            if (wid < 2) {
                float v = (lane < NWARP) ? red[wid * 32 + lane] : 0.f;
                #pragma unroll
                for (int off = 8; off > 0; off >>= 1)
                    v += __shfl_xor_sync(0xFFFFFFFFu, v, off);
                if (lane == 0) aux[wid] = 1.0f / v;
            }
            __syncthreads();   // E + aux visible
        }

        // ---- weighted sum: warp = (r-half, oc-pair); E read once per 2 oc ----
        {
            const __half2* pc0 = Pp + woc0 * PSTR2;
            const __half2* pc1 = Pp + woc1 * PSTR2;
            float a00 = 0.f, a01 = 0.f, a10 = 0.f, a11 = 0.f;
            #pragma unroll 3
            for (int rr = rst + lane; rr < rst + NR / 2; rr += 32) {
                const float e0 = E0[rr];
                const float e1 = E1[rr];
                const float2 p0 = __half22float2(pc0[rr]);
                const float2 p1 = __half22float2(pc1[rr]);
                a00 = fmaf(e0, p0.x, a00);
                a01 = fmaf(e0, p1.x, a01);
                a10 = fmaf(e1, p0.y, a10);
                a11 = fmaf(e1, p1.y, a11);
            }
            #pragma unroll
            for (int off = 16; off > 0; off >>= 1) {
                a00 += __shfl_xor_sync(0xFFFFFFFFu, a00, off);
                a01 += __shfl_xor_sync(0xFFFFFFFFu, a01, off);
                a10 += __shfl_xor_sync(0xFFFFFFFFu, a10, off);
                a11 += __shfl_xor_sync(0xFFFFFFFFu, a11, off);
            }
            if (lane == 0) {
                S2[wsrh * 32 + woc0]      = a00;   // batch 0
                S2[wsrh * 32 + woc1]      = a01;
                S2[wsrh * 32 + 16 + woc0] = a10;   // batch 1
                S2[wsrh * 32 + 16 + woc1] = a11;
            }
        }
        __syncthreads();

        // ---- squash (warp 0; lanes 0-15 b0, 16-31 b1) ----
        if (wid == 0) {
            float sv = (S2[lane] + S2[32 + lane]) * aux[lane >> 4];
            float sq = sv * sv;
            #pragma unroll
            for (int off = 8; off > 0; off >>= 1)
                sq += __shfl_xor_sync(0xFFFFFFFFu, sq, off);
            const float sc = sq / ((1.f + sq) * sqrtf(sq));
            V[lane] = sv * sc;
        }
        __syncthreads();
    }

    // ============ Phase 3: output ============================================
    if (tid < 2 * OC) {
        const int obb = tid >> 4;
        out[((size_t)(b0 + obb) * NC + c) * OC + (tid & 15)] = V[tid];
    }
}

extern "C" void kernel_launch(void* const* d_in, const int* in_sizes, int n_in,
                              void* d_out, int out_size)
{
    (void)in_sizes; (void)n_in; (void)out_size;
    const float* x = (const float*)d_in[0];
    const float* W = (const float*)d_in[1];
    float* out = (float*)d_out;

    static int smem_set = 0;
    const int smem_bytes = SMEM_FLOATS * sizeof(float);
    if (!smem_set) {
        cudaFuncSetAttribute(caps_route_kernel,
                             cudaFuncAttributeMaxDynamicSharedMemorySize,
                             smem_bytes);
        smem_set = 1;
    }

    dim3 grid(NB / BT, NC);
    caps_route_kernel<<<grid, THREADS, smem_bytes>>>(x, W, out);
}